// round 15
// baseline (speedup 1.0000x reference)
#include <cuda_runtime.h>
#include <cuda_fp16.h>
#include <math.h>
#include <stdint.h>

#define S 256
#define NB 128
#define D 256
#define L 8
#define EPS 1e-8f
typedef unsigned long long ull;
typedef unsigned int uint;

#define FMA2(d_, a_, b_, c_) asm("fma.rn.f32x2 %0, %1, %2, %3;" : "=l"(d_) : "l"(a_), "l"(b_), "l"(c_))
#define ADD2(d_, a_, b_) asm("add.rn.f32x2 %0, %1, %2;" : "=l"(d_) : "l"(a_), "l"(b_))
#define UNPACK2(lo_, hi_, p_) asm("mov.b64 {%0, %1}, %2;" : "=f"(lo_), "=f"(hi_) : "l"(p_))

#define LDX4(r, addr) \
  asm volatile("ldmatrix.sync.aligned.m8n8.x4.shared.b16 {%0,%1,%2,%3}, [%4];" \
    : "=r"((r)[0]),"=r"((r)[1]),"=r"((r)[2]),"=r"((r)[3]) : "r"(addr))

#define MMAH(d, a, b0_, b1_) \
  asm volatile("mma.sync.aligned.m16n8k16.row.col.f32.f16.f16.f32 " \
    "{%0,%1,%2,%3}, {%4,%5,%6,%7}, {%8,%9}, {%0,%1,%2,%3};" \
    : "+f"((d)[0]),"+f"((d)[1]),"+f"((d)[2]),"+f"((d)[3]) \
    : "r"((a)[0]),"r"((a)[1]),"r"((a)[2]),"r"((a)[3]), "r"(b0_),"r"(b1_))

__device__ __forceinline__ uint32_t smem_u32(const void* p){
  uint32_t a;
  asm("{ .reg .u64 t; cvta.to.shared.u64 t, %1; cvt.u32.u64 %0, t; }" : "=r"(a) : "l"(p));
  return a;
}
__device__ __forceinline__ uint enc_f(float x){
  uint u = __float_as_uint(x);
  return (u & 0x80000000u) ? ~u : (u | 0x80000000u);
}
__device__ __forceinline__ float dec_f(uint u){
  return __uint_as_float((u & 0x80000000u) ? (u & 0x7FFFFFFFu) : ~u);
}
__device__ __forceinline__ uint packh(__half a, __half b){
  return (uint)__half_as_ushort(a) | ((uint)__half_as_ushort(b) << 16);
}

// ---- scratch ----
__device__ __align__(16) float g_np[2][S][NB][33];
__device__ __align__(16) float g_nq[2][S][NB][33];
__device__ __align__(16) float g_alpha[2][NB][S][S];
__device__ __align__(16) float g_rowsum[2][NB][S];
__device__ __align__(16) ull   g_pack[2][NB][S];
__device__ __align__(16) uint  g_mp[2][NB][S][L];
__device__ __align__(16) float g_h[2][NB][S][D];
__device__ __align__(16) __half g_qhi[2][NB][S][D];   // [t][d]
__device__ __align__(16) __half g_qlo[2][NB][S][D];
__device__ __align__(16) __half g_qthi[2][NB][D][S];  // [d][t]

// ---------------- k_split: Q -> fp16 hi/lo + transposed hi; also zeroes atomics ----------------
__global__ void __launch_bounds__(256) k_split(const float* __restrict__ Q){
  __shared__ unsigned short sth[256*33];
  int b = blockIdx.y, dir = blockIdx.z;
  int tid = threadIdx.x;
  { // init atomically-combined buffers (consumed by k_main, launched later)
    int gb = (blockIdx.z*NB + blockIdx.y)*8 + blockIdx.x;  // 0..2047
    int base = gb*256 + tid;                                // 0..524287
    (&g_mp[0][0][0][0])[base] = 0u;
    if (base < 2*NB*S){
      (&g_pack[0][0][0])[base] = 0ULL;
      (&g_rowsum[0][0][0])[base] = 0.f;
    }
  }
  int tl = tid>>3, d0 = (tid&7)*32;
  int t = blockIdx.x*32 + tl;
  const float4* src = (const float4*)(Q + (size_t)(t*NB + b)*512 + dir*256 + d0);
  unsigned short hbuf[32], lbuf[32];
  #pragma unroll
  for (int k=0;k<8;k++){
    float4 v = src[k];
    float xs[4] = {v.x, v.y, v.z, v.w};
    #pragma unroll
    for (int j=0;j<4;j++){
      __half h = __float2half_rn(xs[j]);
      __half lo = __float2half_rn(xs[j] - __half2float(h));
      int idx = 4*k+j;
      hbuf[idx] = __half_as_ushort(h);
      lbuf[idx] = __half_as_ushort(lo);
      sth[(d0+idx)*33 + tl] = hbuf[idx];
    }
  }
  size_t qi = ((size_t)(dir*NB+b)*256 + t)*256 + d0;
  #pragma unroll
  for (int k=0;k<4;k++){
    ((uint4*)(&g_qhi[0][0][0][0] + qi))[k] = ((uint4*)hbuf)[k];
    ((uint4*)(&g_qlo[0][0][0][0] + qi))[k] = ((uint4*)lbuf)[k];
  }
  __syncthreads();
  int d = tid;
  unsigned short th[32];
  #pragma unroll
  for (int j=0;j<32;j++) th[j]=sth[d*33+j];
  size_t qti = ((size_t)(dir*NB+b)*256 + d)*256 + blockIdx.x*32;
  #pragma unroll
  for (int k=0;k<4;k++)
    ((uint4*)(&g_qthi[0][0][0][0] + qti))[k] = ((uint4*)th)[k];
}

// ---------------- K1: weighted norms, GEMM-tiled, 16 rows/block ----------------
#define PXP 133
#define PWP 133

__global__ void __launch_bounds__(128) k_norms(const float* __restrict__ P,
                                               const float* __restrict__ Q,
                                               const float* __restrict__ W){
  __shared__ ull sw[32*PWP];   // [ch 0..31][pair]
  __shared__ ull sx[16*PXP];   // [row][pair]
  int tensor = blockIdx.y, dir = blockIdx.z;
  int rBase = blockIdx.x*16;
  const float* X = tensor ? Q : P;
  float* dst = tensor ? &g_nq[0][0][0][0] : &g_np[0][0][0][0];
  int tid = threadIdx.x;
  int wrows[4] = {dir, 2+dir, 4, 5};

  for (int i=tid; i<32*128; i+=128){
    int ch = i>>7, pr128 = i&127;
    int dq = pr128>>5, pr = pr128&31;
    int a = ch>>3, l = ch&7;
    float2 w = *(const float2*)&W[(size_t)wrows[a]*2048 + l*256 + 2*pr128];
    *(float2*)&sw[ch*PWP + dq*33 + pr] = make_float2(w.x*w.x, w.y*w.y);
  }
  {
    int r = tid>>3, h8 = tid&7;
    int q = h8>>1, sub = h8&1;
    const float4* src = (const float4*)(X + (size_t)(rBase+r)*512 + dir*256 + q*64 + sub*32);
    ull* xrow = sx + r*PXP + q*33 + sub*16;
    #pragma unroll
    for (int k=0;k<8;k++){
      float4 v = src[k];
      *(float2*)&xrow[2*k]   = make_float2(v.x*v.x, v.y*v.y);
      *(float2*)&xrow[2*k+1] = make_float2(v.z*v.z, v.w*v.w);
    }
  }
  __syncthreads();

  int dq = tid&3, cg = (tid>>2)&3, rg = tid>>4;  // rg 0..7, 2 rows each
  const ull* xr0 = sx + (rg*2+0)*PXP + dq*33;
  const ull* xr1 = sx + (rg*2+1)*PXP + dq*33;
  const ull* wbase = sw + (cg*8)*PWP + dq*33;

  ull acc[2][8];
  ull uacc[2];
  #pragma unroll
  for (int i=0;i<2;i++){
    uacc[i]=0ULL;
    #pragma unroll
    for (int l=0;l<8;l++) acc[i][l]=0ULL;
  }
  #pragma unroll 4
  for (int pr=0; pr<32; pr++){
    ull x0 = xr0[pr], x1 = xr1[pr];
    if (cg==0){
      ADD2(uacc[0], uacc[0], x0);
      ADD2(uacc[1], uacc[1], x1);
    }
    #pragma unroll
    for (int l=0;l<8;l++){
      ull w = wbase[l*PWP + pr];
      FMA2(acc[0][l], x0, w, acc[0][l]);
      FMA2(acc[1][l], x1, w, acc[1][l]);
    }
  }
  #pragma unroll
  for (int i=0;i<2;i++){
    float v[9];
    #pragma unroll
    for (int l=0;l<8;l++){
      float lo,hi; UNPACK2(lo,hi,acc[i][l]);
      v[l] = lo+hi;
    }
    { float lo,hi; UNPACK2(lo,hi,uacc[i]); v[8] = lo+hi; }
    #pragma unroll
    for (int off=1; off<4; off<<=1){
      #pragma unroll
      for (int l=0;l<9;l++) v[l] += __shfl_xor_sync(0xffffffffu, v[l], off);
    }
    if (dq==0){
      int r = rBase + rg*2 + i;
      float* o = dst + ((size_t)(dir*S*NB) + r)*33;
      #pragma unroll
      for (int l=0;l<8;l++) o[cg*8+l] = sqrtf(v[l]);
      if (cg==0) o[32] = sqrtf(v[8]);
    }
  }
}

// ---------------- k_main_mma: channel-paired maxpool + 3-term alpha ----------------
#define BPITCH 528
#define OFF_BHI 0
#define OFF_BLO 67584
#define OFF_AHI 135168
#define OFF_ALO 168960
#define OFF_W2S 202752
#define OFF_QNS 210944
#define OFF_PNS 215552
#define SM_MM   217856

__global__ void __launch_bounds__(256) k_main_mma(const float* __restrict__ P,
                                                  const float* __restrict__ W,
                                                  float* __restrict__ out){
  extern __shared__ char smem[];
  float* sW2 = (float*)(smem + OFF_W2S);
  float* sQn = (float*)(smem + OFF_QNS);
  float* sPn = (float*)(smem + OFF_PNS);

  int sTile = blockIdx.x >> 1, tHalf = blockIdx.x & 1;
  int b = blockIdx.y, dir = blockIdx.z;
  int sBase = sTile*64, tBase = tHalf*128;
  int tid = threadIdx.x, wid = tid>>5, lane = tid&31;
  int swS = (wid>>1)*16;
  int twT = (wid&1)*64;

  for (int i=tid;i<8*256;i+=256){
    float w = W[(size_t)(2+dir)*2048 + i];
    sW2[i] = w*w;
  }
  for (int i=tid;i<9*128;i+=256){
    int c=i>>7, t=i&127;
    sQn[i] = 1.0f / g_nq[dir][tBase+t][b][(c<8)?(8+c):32];
  }
  for (int i=tid;i<9*64;i+=256){
    int c=i/64, r=i%64;
    sPn[i] = 1.0f / g_np[dir][sBase+r][b][(c<8)?(8+c):32];
  }
  { // B tiles: q hi/lo fp16 [128 t][256 d]
    int r = tid>>1, h = tid&1;
    size_t qi = ((size_t)(dir*NB+b)*256 + tBase + r)*256 + h*128;
    const uint4* shi = (const uint4*)(&g_qhi[0][0][0][0] + qi);
    const uint4* slo = (const uint4*)(&g_qlo[0][0][0][0] + qi);
    char* dh = smem + OFF_BHI + r*BPITCH + h*256;
    char* dl = smem + OFF_BLO + r*BPITCH + h*256;
    #pragma unroll
    for (int k=0;k<16;k++){
      *(uint4*)(dh + 16*k) = shi[k];
      *(uint4*)(dl + 16*k) = slo[k];
    }
  }
  float preg[64];
  int prow = tid>>2, pcb = tid&3;
  {
    const float4* src = (const float4*)(P + ((size_t)(sBase+prow)*NB + b)*512 + dir*256 + pcb*64);
    #pragma unroll
    for (int k=0;k<16;k++){
      float4 v = src[k];
      preg[4*k+0]=v.x; preg[4*k+1]=v.y; preg[4*k+2]=v.z; preg[4*k+3]=v.w;
    }
  }

  uint32_t aHb = smem_u32(smem + OFF_AHI);
  uint32_t aLb = smem_u32(smem + OFF_ALO);
  uint32_t bHb = smem_u32(smem + OFF_BHI);
  uint32_t bLb = smem_u32(smem + OFF_BLO);

  uint32_t arow = swS + (lane&15);
  uint32_t acolx = ((lane&16)?16:0);
  uint32_t aoffH = aHb + arow*BPITCH + acolx;
  uint32_t aoffL = aLb + arow*BPITCH + acolx;
  uint32_t brow_b = (lane&7) + ((lane&16)>>1);
  uint32_t bcolx = ((lane&8)?16:0);

  int rl0 = swS + (lane>>2), rl1 = rl0 + 8;

  for (int pg=0; pg<5; pg++){
    __syncthreads();
    if (pg < 4){
      int c0 = pg*2, c1 = c0+1;
      { // build A for BOTH channels: c0 -> AHI, c1 -> ALO
        char* dh = smem + OFF_AHI + prow*BPITCH + pcb*128;
        char* dl = smem + OFF_ALO + prow*BPITCH + pcb*128;
        const float* w0 = sW2 + c0*256 + pcb*64;
        const float* w1 = sW2 + c1*256 + pcb*64;
        #pragma unroll
        for (int j=0;j<16;j++){
          __half a0 = __float2half_rn(preg[4*j+0]*w0[4*j+0]);
          __half a1 = __float2half_rn(preg[4*j+1]*w0[4*j+1]);
          __half a2 = __float2half_rn(preg[4*j+2]*w0[4*j+2]);
          __half a3 = __float2half_rn(preg[4*j+3]*w0[4*j+3]);
          __half b0 = __float2half_rn(preg[4*j+0]*w1[4*j+0]);
          __half b1 = __float2half_rn(preg[4*j+1]*w1[4*j+1]);
          __half b2 = __float2half_rn(preg[4*j+2]*w1[4*j+2]);
          __half b3 = __float2half_rn(preg[4*j+3]*w1[4*j+3]);
          *(uint2*)(dh + 8*j) = make_uint2(packh(a0,a1), packh(a2,a3));
          *(uint2*)(dl + 8*j) = make_uint2(packh(b0,b1), packh(b2,b3));
        }
      }
      __syncthreads();

      float acc0[8][4], acc1[8][4];
      #pragma unroll
      for (int nt=0;nt<8;nt++){
        acc0[nt][0]=0.f;acc0[nt][1]=0.f;acc0[nt][2]=0.f;acc0[nt][3]=0.f;
        acc1[nt][0]=0.f;acc1[nt][1]=0.f;acc1[nt][2]=0.f;acc1[nt][3]=0.f;
      }
      for (int kc=0; kc<16; kc++){
        uint32_t a0[4], a1[4];
        LDX4(a0, aoffH + kc*32);
        LDX4(a1, aoffL + kc*32);
        uint32_t bh[4][4];
        #pragma unroll
        for (int g=0; g<4; g++){
          uint32_t boff = (twT + g*16 + brow_b)*BPITCH + kc*32 + bcolx;
          LDX4(bh[g], bHb + boff);
        }
        #pragma unroll
        for (int g=0; g<4; g++){
          MMAH(acc0[2*g],   a0, bh[g][0], bh[g][1]);
          MMAH(acc0[2*g+1], a0, bh[g][2], bh[g][3]);
        }
        #pragma unroll
        for (int g=0; g<4; g++){
          MMAH(acc1[2*g],   a1, bh[g][0], bh[g][1]);
          MMAH(acc1[2*g+1], a1, bh[g][2], bh[g][3]);
        }
      }
      #pragma unroll
      for (int ci=0; ci<2; ci++){
        int c = c0 + ci;
        float (*ac)[4] = ci ? acc1 : acc0;
        float m0=-3.4e38f, m1=-3.4e38f;
        const float* qn = sQn + c*128;
        #pragma unroll
        for (int nt=0;nt<8;nt++){
          int col = twT + nt*8 + 2*(lane&3);
          float q0 = qn[col], q1 = qn[col+1];
          m0 = fmaxf(m0, fmaxf(ac[nt][0]*q0, ac[nt][1]*q1));
          m1 = fmaxf(m1, fmaxf(ac[nt][2]*q0, ac[nt][3]*q1));
        }
        #pragma unroll
        for (int off=1; off<4; off<<=1){
          m0 = fmaxf(m0, __shfl_xor_sync(0xffffffffu, m0, off));
          m1 = fmaxf(m1, __shfl_xor_sync(0xffffffffu, m1, off));
        }
        if ((lane&3)==0){
          atomicMax(&g_mp[dir][b][sBase+rl0][c], enc_f(m0 * sPn[c*64+rl0]));
          atomicMax(&g_mp[dir][b][sBase+rl1][c], enc_f(m1 * sPn[c*64+rl1]));
        }
      }
    } else {
      { // build alpha A: p hi -> AHI, p lo -> ALO
        char* dh = smem + OFF_AHI + prow*BPITCH + pcb*128;
        char* dl = smem + OFF_ALO + prow*BPITCH + pcb*128;
        #pragma unroll
        for (int j=0;j<16;j++){
          float a0=preg[4*j+0], a1=preg[4*j+1], a2=preg[4*j+2], a3=preg[4*j+3];
          __half h0 = __float2half_rn(a0), h1 = __float2half_rn(a1);
          __half h2 = __float2half_rn(a2), h3 = __float2half_rn(a3);
          __half l0 = __float2half_rn(a0 - __half2float(h0));
          __half l1 = __float2half_rn(a1 - __half2float(h1));
          __half l2 = __float2half_rn(a2 - __half2float(h2));
          __half l3 = __float2half_rn(a3 - __half2float(h3));
          *(uint2*)(dh + 8*j) = make_uint2(packh(h0,h1), packh(h2,h3));
          *(uint2*)(dl + 8*j) = make_uint2(packh(l0,l1), packh(l2,l3));
        }
      }
      __syncthreads();

      float acc[8][4];
      #pragma unroll
      for (int nt=0;nt<8;nt++){ acc[nt][0]=0.f;acc[nt][1]=0.f;acc[nt][2]=0.f;acc[nt][3]=0.f; }

      for (int kc=0; kc<16; kc++){
        uint32_t ah[4], al[4];
        LDX4(ah, aoffH + kc*32);
        LDX4(al, aoffL + kc*32);
        uint32_t bh[4][4], bl[4][4];
        #pragma unroll
        for (int g=0; g<4; g++){
          uint32_t boff = (twT + g*16 + brow_b)*BPITCH + kc*32 + bcolx;
          LDX4(bh[g], bHb + boff);
          LDX4(bl[g], bLb + boff);
        }
        #pragma unroll
        for (int g=0; g<4; g++){
          MMAH(acc[2*g],   ah, bh[g][0], bh[g][1]);
          MMAH(acc[2*g+1], ah, bh[g][2], bh[g][3]);
        }
        #pragma unroll
        for (int g=0; g<4; g++){
          MMAH(acc[2*g],   ah, bl[g][0], bl[g][1]);
          MMAH(acc[2*g+1], ah, bl[g][2], bl[g][3]);
        }
        #pragma unroll
        for (int g=0; g<4; g++){
          MMAH(acc[2*g],   al, bh[g][0], bh[g][1]);
          MMAH(acc[2*g+1], al, bh[g][2], bh[g][3]);
        }
      }

      float invp0 = sPn[8*64 + rl0], invp1 = sPn[8*64 + rl1];
      const float* qn = sQn + 8*128;
      float rs0=0.f, rs1=0.f, bv0=-3.4e38f, bv1=-3.4e38f;
      int bi0=0, bi1=0;
      int sg0 = sBase + rl0, sg1 = sBase + rl1;
      float* arow0 = &g_alpha[dir][b][sg0][tBase];
      float* arow1 = &g_alpha[dir][b][sg1][tBase];
      #pragma unroll
      for (int nt=0;nt<8;nt++){
        int col = twT + nt*8 + 2*(lane&3);
        float q0 = qn[col], q1 = qn[col+1];
        float a00 = acc[nt][0]*q0*invp0, a01 = acc[nt][1]*q1*invp0;
        float a10 = acc[nt][2]*q0*invp1, a11 = acc[nt][3]*q1*invp1;
        *(float2*)(arow0 + col) = make_float2(a00, a01);
        *(float2*)(arow1 + col) = make_float2(a10, a11);
        rs0 += a00 + a01; rs1 += a10 + a11;
        int tg = tBase + col;
        if (a00>bv0){bv0=a00;bi0=tg;}
        if (a01>bv0){bv0=a01;bi0=tg+1;}
        if (a10>bv1){bv1=a10;bi1=tg;}
        if (a11>bv1){bv1=a11;bi1=tg+1;}
      }
      #pragma unroll
      for (int off=1; off<4; off<<=1){
        rs0 += __shfl_xor_sync(0xffffffffu, rs0, off);
        rs1 += __shfl_xor_sync(0xffffffffu, rs1, off);
        float ov0 = __shfl_xor_sync(0xffffffffu, bv0, off);
        int   oi0 = __shfl_xor_sync(0xffffffffu, bi0, off);
        if (ov0>bv0 || (ov0==bv0 && oi0<bi0)){bv0=ov0;bi0=oi0;}
        float ov1 = __shfl_xor_sync(0xffffffffu, bv1, off);
        int   oi1 = __shfl_xor_sync(0xffffffffu, bi1, off);
        if (ov1>bv1 || (ov1==bv1 && oi1<bi1)){bv1=ov1;bi1=oi1;}
      }
      if ((lane&3)==0){
        atomicAdd(&g_rowsum[dir][b][sg0], rs0);
        atomicAdd(&g_rowsum[dir][b][sg1], rs1);
        atomicMax(&g_pack[dir][b][sg0], ((ull)enc_f(bv0)<<32) | (uint)(0xFFFFFFFFu - (uint)bi0));
        atomicMax(&g_pack[dir][b][sg1], ((ull)enc_f(bv1)<<32) | (uint)(0xFFFFFFFFu - (uint)bi1));
      }
    }
  }
}

// ---------------- k_hmean_mma: A = alpha hi/lo (2-term), B = qthi ----------------
#define HM_BHI 0
#define HM_AHI 67584
#define HM_ALO 101376
#define SM_HM  135168

__global__ void __launch_bounds__(256) k_hmean_mma(void){
  extern __shared__ char smem[];
  int sTile = blockIdx.x >> 1, dHalf = blockIdx.x & 1;
  int b = blockIdx.y, dir = blockIdx.z;
  int sBase = sTile*64, dBase = dHalf*128;
  int tid = threadIdx.x, wid = tid>>5, lane = tid&31;
  int swS = (wid>>1)*16, twD = (wid&1)*64;

  { // B: qthi [128 d rows][256 t]
    int r = tid>>1, h = tid&1;
    size_t qi = ((size_t)(dir*NB+b)*256 + dBase + r)*256 + h*128;
    const uint4* shi = (const uint4*)(&g_qthi[0][0][0][0] + qi);
    char* dh = smem + HM_BHI + r*BPITCH + h*256;
    #pragma unroll
    for (int k=0;k<16;k++) *(uint4*)(dh + 16*k) = shi[k];
  }
  { // A: alpha [64 s][256 t] fp32 -> fp16 hi/lo
    int prow = tid>>2, pcb = tid&3;
    const float* arow_g = &g_alpha[dir][b][sBase+prow][pcb*64];
    char* dh = smem + HM_AHI + prow*BPITCH + pcb*128;
    char* dl = smem + HM_ALO + prow*BPITCH + pcb*128;
    #pragma unroll
    for (int j=0;j<16;j++){
      float4 v = *(const float4*)(arow_g + 4*j);
      __half h0 = __float2half_rn(v.x), h1 = __float2half_rn(v.y);
      __half h2 = __float2half_rn(v.z), h3 = __float2half_rn(v.w);
      __half l0 = __float2half_rn(v.x - __half2float(h0));
      __half l1 = __float2half_rn(v.y - __half2float(h1));
      __half l2 = __float2half_rn(v.z - __half2float(h2));
      __half l3 = __float2half_rn(v.w - __half2float(h3));
      *(uint2*)(dh + 8*j) = make_uint2(packh(h0,h1), packh(h2,h3));
      *(uint2*)(dl + 8*j) = make_uint2(packh(l0,l1), packh(l2,l3));
    }
  }
  __syncthreads();

  uint32_t aHb = smem_u32(smem + HM_AHI);
  uint32_t aLb = smem_u32(smem + HM_ALO);
  uint32_t bHb = smem_u32(smem + HM_BHI);
  uint32_t arow = swS + (lane&15);
  uint32_t acolx = ((lane&16)?16:0);
  uint32_t aoffH = aHb + arow*BPITCH + acolx;
  uint32_t aoffL = aLb + arow*BPITCH + acolx;
  uint32_t brow_b = (lane&7) + ((lane&16)>>1);
  uint32_t bcolx = ((lane&8)?16:0);

  float acc[8][4];
  #pragma unroll
  for (int nt=0;nt<8;nt++){ acc[nt][0]=0.f;acc[nt][1]=0.f;acc[nt][2]=0.f;acc[nt][3]=0.f; }

  for (int kc=0; kc<16; kc++){
    uint32_t ah[4], al[4];
    LDX4(ah, aoffH + kc*32);
    LDX4(al, aoffL + kc*32);
    uint32_t bh[4][4];
    #pragma unroll
    for (int g=0; g<4; g++){
      uint32_t boff = (twD + g*16 + brow_b)*BPITCH + kc*32 + bcolx;
      LDX4(bh[g], bHb + boff);
    }
    #pragma unroll
    for (int g=0; g<4; g++){
      MMAH(acc[2*g],   ah, bh[g][0], bh[g][1]);
      MMAH(acc[2*g+1], ah, bh[g][2], bh[g][3]);
    }
    #pragma unroll
    for (int g=0; g<4; g++){
      MMAH(acc[2*g],   al, bh[g][0], bh[g][1]);
      MMAH(acc[2*g+1], al, bh[g][2], bh[g][3]);
    }
  }

  int rl0 = swS + (lane>>2), rl1 = rl0 + 8;
  int sg0 = sBase + rl0, sg1 = sBase + rl1;
  float inv0 = 1.0f / g_rowsum[dir][b][sg0];
  float inv1 = 1.0f / g_rowsum[dir][b][sg1];
  #pragma unroll
  for (int nt=0;nt<8;nt++){
    int col = twD + nt*8 + 2*(lane&3);
    int dg = dBase + col;
    *(float2*)&g_h[dir][b][sg0][dg] = make_float2(acc[nt][0]*inv0, acc[nt][1]*inv0);
    *(float2*)&g_h[dir][b][sg1][dg] = make_float2(acc[nt][2]*inv1, acc[nt][3]*inv1);
  }
}

// ---------------- K_epi: 4 s-rows per block ----------------
__global__ void __launch_bounds__(256) k_epi(const float* __restrict__ P,
                                             const float* __restrict__ Q,
                                             const float* __restrict__ W,
                                             float* __restrict__ out){
  int tid=threadIdx.x;
  int s = blockIdx.x*4 + (tid>>6);
  int b = blockIdx.y;
  int dir = (tid>>5)&1, lane = tid&31;
  const float* p  = P + (size_t)(s*NB+b)*512 + dir*256;
  int qpos = dir ? 0 : (S-1);
  const float* qf = Q + (size_t)(qpos*NB+b)*512 + dir*256;
  ull key = g_pack[dir][b][s];
  int ts = (int)(0xFFFFFFFFu - (uint)(key & 0xFFFFFFFFu));
  const float* qm = Q + (size_t)(ts*NB+b)*512 + dir*256;
  const float* h  = &g_h[dir][b][s][0];
  const float* w01 = W + (size_t)dir*2048;
  const float* w4  = W + (size_t)4*2048;
  const float* w5  = W + (size_t)5*2048;
  float aF[8], aA[8], aH[8], aM[8];
  #pragma unroll
  for (int l=0;l<8;l++){ aF[l]=0.f;aA[l]=0.f;aH[l]=0.f;aM[l]=0.f; }
  #pragma unroll
  for (int k=0;k<8;k++){
    int d = lane + 32*k;
    float pv=p[d], qv=qf[d], hv=h[d], mv=qm[d];
    float pq=pv*qv, ph=pv*hv, hh=hv*hv, pm=pv*mv;
    #pragma unroll
    for (int l=0;l<8;l++){
      float wa = w01[l*256+d];
      float wb = w4[l*256+d];
      float wc = w5[l*256+d];
      aF[l] += pq*wa*wa;
      aA[l] += ph*(wb*wb);
      aH[l] += hh*(wb*wb);
      aM[l] += pm*(wc*wc);
    }
  }
  #pragma unroll
  for (int off=16; off; off>>=1){
    #pragma unroll
    for (int l=0;l<8;l++){
      aF[l]+=__shfl_down_sync(0xffffffffu,aF[l],off);
      aA[l]+=__shfl_down_sync(0xffffffffu,aA[l],off);
      aH[l]+=__shfl_down_sync(0xffffffffu,aH[l],off);
      aM[l]+=__shfl_down_sync(0xffffffffu,aM[l],off);
    }
  }
  if (lane==0){
    const float* np_ = &g_np[dir][s][b][0];
    const float* nqf = &g_nq[dir][qpos][b][0];
    const float* nqm = &g_nq[dir][ts][b][0];
    float* o = out + ((size_t)s*NB+b)*64;
    #pragma unroll
    for (int l=0;l<8;l++){
      o[0  + dir*8 + l] = aF[l] / fmaxf(np_[l]    * nqf[l],       EPS);
      o[16 + dir*8 + l] = dec_f(g_mp[dir][b][s][l]);
      o[32 + dir*8 + l] = aA[l] / fmaxf(np_[16+l] * sqrtf(aH[l]), EPS);
      o[48 + dir*8 + l] = aM[l] / fmaxf(np_[24+l] * nqm[24+l],    EPS);
    }
  }
}

extern "C" void kernel_launch(void* const* d_in, const int* in_sizes, int n_in,
                              void* d_out, int out_size){
  const float* P = (const float*)d_in[0];
  const float* Q = (const float*)d_in[1];
  const float* W = (const float*)d_in[2];
  float* out = (float*)d_out;

  cudaFuncSetAttribute(k_main_mma,  cudaFuncAttributeMaxDynamicSharedMemorySize, SM_MM);
  cudaFuncSetAttribute(k_hmean_mma, cudaFuncAttributeMaxDynamicSharedMemorySize, SM_HM);

  k_split<<<dim3(8, NB, 2), 256>>>(Q);
  k_norms<<<dim3(2048, 2, 2), 128>>>(P, Q, W);
  k_main_mma<<<dim3(8, NB, 2), 256, SM_MM>>>(P, W, out);
  k_hmean_mma<<<dim3(8, NB, 2), 256, SM_HM>>>();
  k_epi<<<dim3(64, NB), 256>>>(P, Q, W, out);
}

// round 16
// speedup vs baseline: 1.0214x; 1.0214x over previous
#include <cuda_runtime.h>
#include <cuda_fp16.h>
#include <math.h>
#include <stdint.h>

#define S 256
#define NB 128
#define D 256
#define L 8
#define EPS 1e-8f
typedef unsigned long long ull;
typedef unsigned int uint;

#define FMA2(d_, a_, b_, c_) asm("fma.rn.f32x2 %0, %1, %2, %3;" : "=l"(d_) : "l"(a_), "l"(b_), "l"(c_))
#define ADD2(d_, a_, b_) asm("add.rn.f32x2 %0, %1, %2;" : "=l"(d_) : "l"(a_), "l"(b_))
#define UNPACK2(lo_, hi_, p_) asm("mov.b64 {%0, %1}, %2;" : "=f"(lo_), "=f"(hi_) : "l"(p_))

#define LDX4(r, addr) \
  asm volatile("ldmatrix.sync.aligned.m8n8.x4.shared.b16 {%0,%1,%2,%3}, [%4];" \
    : "=r"((r)[0]),"=r"((r)[1]),"=r"((r)[2]),"=r"((r)[3]) : "r"(addr))

#define MMAH(d, a, b0_, b1_) \
  asm volatile("mma.sync.aligned.m16n8k16.row.col.f32.f16.f16.f32 " \
    "{%0,%1,%2,%3}, {%4,%5,%6,%7}, {%8,%9}, {%0,%1,%2,%3};" \
    : "+f"((d)[0]),"+f"((d)[1]),"+f"((d)[2]),"+f"((d)[3]) \
    : "r"((a)[0]),"r"((a)[1]),"r"((a)[2]),"r"((a)[3]), "r"(b0_),"r"(b1_))

__device__ __forceinline__ uint32_t smem_u32(const void* p){
  uint32_t a;
  asm("{ .reg .u64 t; cvta.to.shared.u64 t, %1; cvt.u32.u64 %0, t; }" : "=r"(a) : "l"(p));
  return a;
}
__device__ __forceinline__ uint enc_f(float x){
  uint u = __float_as_uint(x);
  return (u & 0x80000000u) ? ~u : (u | 0x80000000u);
}
__device__ __forceinline__ float dec_f(uint u){
  return __uint_as_float((u & 0x80000000u) ? (u & 0x7FFFFFFFu) : ~u);
}
__device__ __forceinline__ uint packh(__half a, __half b){
  return (uint)__half_as_ushort(a) | ((uint)__half_as_ushort(b) << 16);
}

// ---- scratch ----
__device__ __align__(16) float g_w2[6][L][D];
__device__ __align__(16) float g_np[2][S][NB][33];
__device__ __align__(16) float g_nq[2][S][NB][33];
__device__ __align__(16) float g_alpha[2][NB][S][S];
__device__ __align__(16) float g_rowsum[2][NB][S];
__device__ __align__(16) ull   g_pack[2][NB][S];
__device__ __align__(16) uint  g_mp[2][NB][S][L];
__device__ __align__(16) float g_h[2][NB][S][D];
__device__ __align__(16) __half g_qhi[2][NB][S][D];   // [t][d]
__device__ __align__(16) __half g_qlo[2][NB][S][D];
__device__ __align__(16) __half g_qthi[2][NB][D][S];  // [d][t]

// ---------------- K0: W^2 ----------------
__global__ void k_w2(const float* __restrict__ W){
  int i = blockIdx.x*blockDim.x + threadIdx.x;
  if (i < 6*L*D){ float w = W[i]; (&g_w2[0][0][0])[i] = w*w; }
}

// ---------------- k_init ----------------
__global__ void k_init(){
  int i = blockIdx.x*1024 + threadIdx.x;
  if (i < 2*NB*S*L) (&g_mp[0][0][0][0])[i] = 0u;
  if (i < 2*NB*S){
    (&g_pack[0][0][0])[i] = 0ULL;
    (&g_rowsum[0][0][0])[i] = 0.f;
  }
}

// ---------------- k_split: Q -> fp16 hi/lo + transposed hi ----------------
__global__ void __launch_bounds__(256) k_split(const float* __restrict__ Q){
  __shared__ unsigned short sth[256*33];
  int b = blockIdx.y, dir = blockIdx.z;
  int tid = threadIdx.x;
  int tl = tid>>3, d0 = (tid&7)*32;
  int t = blockIdx.x*32 + tl;
  const float4* src = (const float4*)(Q + (size_t)(t*NB + b)*512 + dir*256 + d0);
  unsigned short hbuf[32], lbuf[32];
  #pragma unroll
  for (int k=0;k<8;k++){
    float4 v = src[k];
    float xs[4] = {v.x, v.y, v.z, v.w};
    #pragma unroll
    for (int j=0;j<4;j++){
      __half h = __float2half_rn(xs[j]);
      __half lo = __float2half_rn(xs[j] - __half2float(h));
      int idx = 4*k+j;
      hbuf[idx] = __half_as_ushort(h);
      lbuf[idx] = __half_as_ushort(lo);
      sth[(d0+idx)*33 + tl] = hbuf[idx];
    }
  }
  size_t qi = ((size_t)(dir*NB+b)*256 + t)*256 + d0;
  #pragma unroll
  for (int k=0;k<4;k++){
    ((uint4*)(&g_qhi[0][0][0][0] + qi))[k] = ((uint4*)hbuf)[k];
    ((uint4*)(&g_qlo[0][0][0][0] + qi))[k] = ((uint4*)lbuf)[k];
  }
  __syncthreads();
  int d = tid;
  unsigned short th[32];
  #pragma unroll
  for (int j=0;j<32;j++) th[j]=sth[d*33+j];
  size_t qti = ((size_t)(dir*NB+b)*256 + d)*256 + blockIdx.x*32;
  #pragma unroll
  for (int k=0;k<4;k++)
    ((uint4*)(&g_qthi[0][0][0][0] + qti))[k] = ((uint4*)th)[k];
}

// ---------------- K1: weighted norms, GEMM-tiled (R11 winner) ----------------
#define PXP 133
#define PWP 133

__global__ void __launch_bounds__(128) k_norms(const float* __restrict__ P,
                                               const float* __restrict__ Q){
  __shared__ ull sw[32*PWP];
  __shared__ ull sx[32*PXP];
  int tensor = blockIdx.y, dir = blockIdx.z;
  int rBase = blockIdx.x*32;
  const float* X = tensor ? Q : P;
  float* dst = tensor ? &g_nq[0][0][0][0] : &g_np[0][0][0][0];
  int tid = threadIdx.x;
  int wrows[4] = {dir, 2+dir, 4, 5};

  for (int i=tid; i<32*128; i+=128){
    int ch = i>>7, pr128 = i&127;
    int dq = pr128>>5, pr = pr128&31;
    int a = ch>>3, l = ch&7;
    float2 w = *(const float2*)&g_w2[wrows[a]][l][2*pr128];
    *(float2*)&sw[ch*PWP + dq*33 + pr] = w;
  }
  {
    int r = tid>>2, q = tid&3;
    const float4* src = (const float4*)(X + (size_t)(rBase+r)*512 + dir*256 + q*64);
    ull* xrow = sx + r*PXP + q*33;
    #pragma unroll
    for (int k=0;k<16;k++){
      float4 v = src[k];
      *(float2*)&xrow[2*k]   = make_float2(v.x*v.x, v.y*v.y);
      *(float2*)&xrow[2*k+1] = make_float2(v.z*v.z, v.w*v.w);
    }
  }
  __syncthreads();

  int dq = tid&3, cg = (tid>>2)&3, rg = tid>>4;
  const ull* xrows[4];
  #pragma unroll
  for (int i=0;i<4;i++) xrows[i] = sx + (rg*4+i)*PXP + dq*33;
  const ull* wbase = sw + (cg*8)*PWP + dq*33;

  ull acc[4][8];
  ull uacc[4];
  #pragma unroll
  for (int i=0;i<4;i++){
    uacc[i]=0ULL;
    #pragma unroll
    for (int l=0;l<8;l++) acc[i][l]=0ULL;
  }
  #pragma unroll 4
  for (int pr=0; pr<32; pr++){
    ull xv[4];
    #pragma unroll
    for (int i=0;i<4;i++) xv[i] = xrows[i][pr];
    if (cg==0){
      #pragma unroll
      for (int i=0;i<4;i++) ADD2(uacc[i], uacc[i], xv[i]);
    }
    #pragma unroll
    for (int l=0;l<8;l++){
      ull w = wbase[l*PWP + pr];
      #pragma unroll
      for (int i=0;i<4;i++) FMA2(acc[i][l], xv[i], w, acc[i][l]);
    }
  }
  #pragma unroll
  for (int i=0;i<4;i++){
    float v[9];
    #pragma unroll
    for (int l=0;l<8;l++){
      float lo,hi; UNPACK2(lo,hi,acc[i][l]);
      v[l] = lo+hi;
    }
    { float lo,hi; UNPACK2(lo,hi,uacc[i]); v[8] = lo+hi; }
    #pragma unroll
    for (int off=1; off<4; off<<=1){
      #pragma unroll
      for (int l=0;l<9;l++) v[l] += __shfl_xor_sync(0xffffffffu, v[l], off);
    }
    if (dq==0){
      int r = rBase + rg*4 + i;
      float* o = dst + ((size_t)(dir*S*NB) + r)*33;
      #pragma unroll
      for (int l=0;l<8;l++) o[cg*8+l] = sqrtf(v[l]);
      if (cg==0) o[32] = sqrtf(v[8]);
    }
  }
}

// ---------------- k_main_mma: channel-paired maxpool + 3-term alpha (R14) ----------------
#define BPITCH 528
#define OFF_BHI 0
#define OFF_BLO 67584
#define OFF_AHI 135168
#define OFF_ALO 168960
#define OFF_W2S 202752
#define OFF_QNS 210944
#define OFF_PNS 215552
#define SM_MM   217856

__global__ void __launch_bounds__(256) k_main_mma(const float* __restrict__ P,
                                                  float* __restrict__ out){
  extern __shared__ char smem[];
  float* sW2 = (float*)(smem + OFF_W2S);
  float* sQn = (float*)(smem + OFF_QNS);
  float* sPn = (float*)(smem + OFF_PNS);

  int sTile = blockIdx.x >> 1, tHalf = blockIdx.x & 1;
  int b = blockIdx.y, dir = blockIdx.z;
  int sBase = sTile*64, tBase = tHalf*128;
  int tid = threadIdx.x, wid = tid>>5, lane = tid&31;
  int swS = (wid>>1)*16;
  int twT = (wid&1)*64;

  for (int i=tid;i<8*256;i+=256) sW2[i] = g_w2[2+dir][0][i];
  for (int i=tid;i<9*128;i+=256){
    int c=i>>7, t=i&127;
    sQn[i] = 1.0f / g_nq[dir][tBase+t][b][(c<8)?(8+c):32];
  }
  for (int i=tid;i<9*64;i+=256){
    int c=i/64, r=i%64;
    sPn[i] = 1.0f / g_np[dir][sBase+r][b][(c<8)?(8+c):32];
  }
  { // B tiles: q hi/lo fp16 [128 t][256 d]
    int r = tid>>1, h = tid&1;
    size_t qi = ((size_t)(dir*NB+b)*256 + tBase + r)*256 + h*128;
    const uint4* shi = (const uint4*)(&g_qhi[0][0][0][0] + qi);
    const uint4* slo = (const uint4*)(&g_qlo[0][0][0][0] + qi);
    char* dh = smem + OFF_BHI + r*BPITCH + h*256;
    char* dl = smem + OFF_BLO + r*BPITCH + h*256;
    #pragma unroll
    for (int k=0;k<16;k++){
      *(uint4*)(dh + 16*k) = shi[k];
      *(uint4*)(dl + 16*k) = slo[k];
    }
  }
  float preg[64];
  int prow = tid>>2, pcb = tid&3;
  {
    const float4* src = (const float4*)(P + ((size_t)(sBase+prow)*NB + b)*512 + dir*256 + pcb*64);
    #pragma unroll
    for (int k=0;k<16;k++){
      float4 v = src[k];
      preg[4*k+0]=v.x; preg[4*k+1]=v.y; preg[4*k+2]=v.z; preg[4*k+3]=v.w;
    }
  }

  uint32_t aHb = smem_u32(smem + OFF_AHI);
  uint32_t aLb = smem_u32(smem + OFF_ALO);
  uint32_t bHb = smem_u32(smem + OFF_BHI);
  uint32_t bLb = smem_u32(smem + OFF_BLO);

  uint32_t arow = swS + (lane&15);
  uint32_t acolx = ((lane&16)?16:0);
  uint32_t aoffH = aHb + arow*BPITCH + acolx;
  uint32_t aoffL = aLb + arow*BPITCH + acolx;
  uint32_t brow_b = (lane&7) + ((lane&16)>>1);
  uint32_t bcolx = ((lane&8)?16:0);

  int rl0 = swS + (lane>>2), rl1 = rl0 + 8;

  for (int pg=0; pg<5; pg++){
    __syncthreads();
    if (pg < 4){
      int c0 = pg*2, c1 = c0+1;
      {
        char* dh = smem + OFF_AHI + prow*BPITCH + pcb*128;
        char* dl = smem + OFF_ALO + prow*BPITCH + pcb*128;
        const float* w0 = sW2 + c0*256 + pcb*64;
        const float* w1 = sW2 + c1*256 + pcb*64;
        #pragma unroll
        for (int j=0;j<16;j++){
          __half a0 = __float2half_rn(preg[4*j+0]*w0[4*j+0]);
          __half a1 = __float2half_rn(preg[4*j+1]*w0[4*j+1]);
          __half a2 = __float2half_rn(preg[4*j+2]*w0[4*j+2]);
          __half a3 = __float2half_rn(preg[4*j+3]*w0[4*j+3]);
          __half b0 = __float2half_rn(preg[4*j+0]*w1[4*j+0]);
          __half b1 = __float2half_rn(preg[4*j+1]*w1[4*j+1]);
          __half b2 = __float2half_rn(preg[4*j+2]*w1[4*j+2]);
          __half b3 = __float2half_rn(preg[4*j+3]*w1[4*j+3]);
          *(uint2*)(dh + 8*j) = make_uint2(packh(a0,a1), packh(a2,a3));
          *(uint2*)(dl + 8*j) = make_uint2(packh(b0,b1), packh(b2,b3));
        }
      }
      __syncthreads();

      float acc0[8][4], acc1[8][4];
      #pragma unroll
      for (int nt=0;nt<8;nt++){
        acc0[nt][0]=0.f;acc0[nt][1]=0.f;acc0[nt][2]=0.f;acc0[nt][3]=0.f;
        acc1[nt][0]=0.f;acc1[nt][1]=0.f;acc1[nt][2]=0.f;acc1[nt][3]=0.f;
      }
      for (int kc=0; kc<16; kc++){
        uint32_t a0[4], a1[4];
        LDX4(a0, aoffH + kc*32);
        LDX4(a1, aoffL + kc*32);
        uint32_t bh[4][4];
        #pragma unroll
        for (int g=0; g<4; g++){
          uint32_t boff = (twT + g*16 + brow_b)*BPITCH + kc*32 + bcolx;
          LDX4(bh[g], bHb + boff);
        }
        #pragma unroll
        for (int g=0; g<4; g++){
          MMAH(acc0[2*g],   a0, bh[g][0], bh[g][1]);
          MMAH(acc0[2*g+1], a0, bh[g][2], bh[g][3]);
        }
        #pragma unroll
        for (int g=0; g<4; g++){
          MMAH(acc1[2*g],   a1, bh[g][0], bh[g][1]);
          MMAH(acc1[2*g+1], a1, bh[g][2], bh[g][3]);
        }
      }
      #pragma unroll
      for (int ci=0; ci<2; ci++){
        int c = c0 + ci;
        float (*ac)[4] = ci ? acc1 : acc0;
        float m0=-3.4e38f, m1=-3.4e38f;
        const float* qn = sQn + c*128;
        #pragma unroll
        for (int nt=0;nt<8;nt++){
          int col = twT + nt*8 + 2*(lane&3);
          float q0 = qn[col], q1 = qn[col+1];
          m0 = fmaxf(m0, fmaxf(ac[nt][0]*q0, ac[nt][1]*q1));
          m1 = fmaxf(m1, fmaxf(ac[nt][2]*q0, ac[nt][3]*q1));
        }
        #pragma unroll
        for (int off=1; off<4; off<<=1){
          m0 = fmaxf(m0, __shfl_xor_sync(0xffffffffu, m0, off));
          m1 = fmaxf(m1, __shfl_xor_sync(0xffffffffu, m1, off));
        }
        if ((lane&3)==0){
          atomicMax(&g_mp[dir][b][sBase+rl0][c], enc_f(m0 * sPn[c*64+rl0]));
          atomicMax(&g_mp[dir][b][sBase+rl1][c], enc_f(m1 * sPn[c*64+rl1]));
        }
      }
    } else {
      {
        char* dh = smem + OFF_AHI + prow*BPITCH + pcb*128;
        char* dl = smem + OFF_ALO + prow*BPITCH + pcb*128;
        #pragma unroll
        for (int j=0;j<16;j++){
          float a0=preg[4*j+0], a1=preg[4*j+1], a2=preg[4*j+2], a3=preg[4*j+3];
          __half h0 = __float2half_rn(a0), h1 = __float2half_rn(a1);
          __half h2 = __float2half_rn(a2), h3 = __float2half_rn(a3);
          __half l0 = __float2half_rn(a0 - __half2float(h0));
          __half l1 = __float2half_rn(a1 - __half2float(h1));
          __half l2 = __float2half_rn(a2 - __half2float(h2));
          __half l3 = __float2half_rn(a3 - __half2float(h3));
          *(uint2*)(dh + 8*j) = make_uint2(packh(h0,h1), packh(h2,h3));
          *(uint2*)(dl + 8*j) = make_uint2(packh(l0,l1), packh(l2,l3));
        }
      }
      __syncthreads();

      float acc[8][4];
      #pragma unroll
      for (int nt=0;nt<8;nt++){ acc[nt][0]=0.f;acc[nt][1]=0.f;acc[nt][2]=0.f;acc[nt][3]=0.f; }

      for (int kc=0; kc<16; kc++){
        uint32_t ah[4], al[4];
        LDX4(ah, aoffH + kc*32);
        LDX4(al, aoffL + kc*32);
        uint32_t bh[4][4], bl[4][4];
        #pragma unroll
        for (int g=0; g<4; g++){
          uint32_t boff = (twT + g*16 + brow_b)*BPITCH + kc*32 + bcolx;
          LDX4(bh[g], bHb + boff);
          LDX4(bl[g], bLb + boff);
        }
        #pragma unroll
        for (int g=0; g<4; g++){
          MMAH(acc[2*g],   ah, bh[g][0], bh[g][1]);
          MMAH(acc[2*g+1], ah, bh[g][2], bh[g][3]);
        }
        #pragma unroll
        for (int g=0; g<4; g++){
          MMAH(acc[2*g],   ah, bl[g][0], bl[g][1]);
          MMAH(acc[2*g+1], ah, bl[g][2], bl[g][3]);
        }
        #pragma unroll
        for (int g=0; g<4; g++){
          MMAH(acc[2*g],   al, bh[g][0], bh[g][1]);
          MMAH(acc[2*g+1], al, bh[g][2], bh[g][3]);
        }
      }

      float invp0 = sPn[8*64 + rl0], invp1 = sPn[8*64 + rl1];
      const float* qn = sQn + 8*128;
      float rs0=0.f, rs1=0.f, bv0=-3.4e38f, bv1=-3.4e38f;
      int bi0=0, bi1=0;
      int sg0 = sBase + rl0, sg1 = sBase + rl1;
      float* arow0 = &g_alpha[dir][b][sg0][tBase];
      float* arow1 = &g_alpha[dir][b][sg1][tBase];
      #pragma unroll
      for (int nt=0;nt<8;nt++){
        int col = twT + nt*8 + 2*(lane&3);
        float q0 = qn[col], q1 = qn[col+1];
        float a00 = acc[nt][0]*q0*invp0, a01 = acc[nt][1]*q1*invp0;
        float a10 = acc[nt][2]*q0*invp1, a11 = acc[nt][3]*q1*invp1;
        *(float2*)(arow0 + col) = make_float2(a00, a01);
        *(float2*)(arow1 + col) = make_float2(a10, a11);
        rs0 += a00 + a01; rs1 += a10 + a11;
        int tg = tBase + col;
        if (a00>bv0){bv0=a00;bi0=tg;}
        if (a01>bv0){bv0=a01;bi0=tg+1;}
        if (a10>bv1){bv1=a10;bi1=tg;}
        if (a11>bv1){bv1=a11;bi1=tg+1;}
      }
      #pragma unroll
      for (int off=1; off<4; off<<=1){
        rs0 += __shfl_xor_sync(0xffffffffu, rs0, off);
        rs1 += __shfl_xor_sync(0xffffffffu, rs1, off);
        float ov0 = __shfl_xor_sync(0xffffffffu, bv0, off);
        int   oi0 = __shfl_xor_sync(0xffffffffu, bi0, off);
        if (ov0>bv0 || (ov0==bv0 && oi0<bi0)){bv0=ov0;bi0=oi0;}
        float ov1 = __shfl_xor_sync(0xffffffffu, bv1, off);
        int   oi1 = __shfl_xor_sync(0xffffffffu, bi1, off);
        if (ov1>bv1 || (ov1==bv1 && oi1<bi1)){bv1=ov1;bi1=oi1;}
      }
      if ((lane&3)==0){
        atomicAdd(&g_rowsum[dir][b][sg0], rs0);
        atomicAdd(&g_rowsum[dir][b][sg1], rs1);
        atomicMax(&g_pack[dir][b][sg0], ((ull)enc_f(bv0)<<32) | (uint)(0xFFFFFFFFu - (uint)bi0));
        atomicMax(&g_pack[dir][b][sg1], ((ull)enc_f(bv1)<<32) | (uint)(0xFFFFFFFFu - (uint)bi1));
      }
    }
  }
}

// ---------------- k_hmean_mma: 64s x 64d CTA, 2 CTAs/SM ----------------
// grid (16 = 4 sTiles x 4 dQuarters, NB, 2). smem = 3*33792 = 101376.
#define HM_BHI 0
#define HM_AHI 33792
#define HM_ALO 67584
#define SM_HM  101376

__global__ void __launch_bounds__(256) k_hmean_mma(void){
  extern __shared__ char smem[];
  int sTile = blockIdx.x >> 2, dQ = blockIdx.x & 3;
  int b = blockIdx.y, dir = blockIdx.z;
  int sBase = sTile*64, dBase = dQ*64;
  int tid = threadIdx.x, wid = tid>>5, lane = tid&31;
  int swS = (wid>>1)*16, twD = (wid&1)*32;

  { // B: qthi [64 d rows][256 t]
    int r = tid>>2, h = tid&3;
    size_t qi = ((size_t)(dir*NB+b)*256 + dBase + r)*256 + h*64;
    const uint4* shi = (const uint4*)(&g_qthi[0][0][0][0] + qi);
    char* dh = smem + HM_BHI + r*BPITCH + h*128;
    #pragma unroll
    for (int k=0;k<8;k++) *(uint4*)(dh + 16*k) = shi[k];
  }
  { // A: alpha [64 s][256 t] fp32 -> fp16 hi/lo
    int prow = tid>>2, pcb = tid&3;
    const float* arow_g = &g_alpha[dir][b][sBase+prow][pcb*64];
    char* dh = smem + HM_AHI + prow*BPITCH + pcb*128;
    char* dl = smem + HM_ALO + prow*BPITCH + pcb*128;
    #pragma unroll
    for (int j=0;j<16;j++){
      float4 v = *(const float4*)(arow_g + 4*j);
      __half h0 = __float2half_rn(v.x), h1 = __float2half_rn(v.y);
      __half h2 = __float2half_rn(v.z), h3 = __float2half_rn(v.w);
      __half l0 = __float2half_rn(v.x - __half2float(h0));
      __half l1 = __float2half_rn(v.y - __half2float(h1));
      __half l2 = __float2half_rn(v.z - __half2float(h2));
      __half l3 = __float2half_rn(v.w - __half2float(h3));
      *(uint2*)(dh + 8*j) = make_uint2(packh(h0,h1), packh(h2,h3));
      *(uint2*)(dl + 8*j) = make_uint2(packh(l0,l1), packh(l2,l3));
    }
  }
  __syncthreads();

  uint32_t aHb = smem_u32(smem + HM_AHI);
  uint32_t aLb = smem_u32(smem + HM_ALO);
  uint32_t bHb = smem_u32(smem + HM_BHI);
  uint32_t arow = swS + (lane&15);
  uint32_t acolx = ((lane&16)?16:0);
  uint32_t aoffH = aHb + arow*BPITCH + acolx;
  uint32_t aoffL = aLb + arow*BPITCH + acolx;
  uint32_t brow_b = (lane&7) + ((lane&16)>>1);
  uint32_t bcolx = ((lane&8)?16:0);

  float acc[4][4];
  #pragma unroll
  for (int nt=0;nt<4;nt++){ acc[nt][0]=0.f;acc[nt][1]=0.f;acc[nt][2]=0.f;acc[nt][3]=0.f; }

  for (int kc=0; kc<16; kc++){
    uint32_t ah[4], al[4];
    LDX4(ah, aoffH + kc*32);
    LDX4(al, aoffL + kc*32);
    uint32_t bh[2][4];
    #pragma unroll
    for (int g=0; g<2; g++){
      uint32_t boff = (twD + g*16 + brow_b)*BPITCH + kc*32 + bcolx;
      LDX4(bh[g], bHb + boff);
    }
    #pragma unroll
    for (int g=0; g<2; g++){
      MMAH(acc[2*g],   ah, bh[g][0], bh[g][1]);
      MMAH(acc[2*g+1], ah, bh[g][2], bh[g][3]);
    }
    #pragma unroll
    for (int g=0; g<2; g++){
      MMAH(acc[2*g],   al, bh[g][0], bh[g][1]);
      MMAH(acc[2*g+1], al, bh[g][2], bh[g][3]);
    }
  }

  int rl0 = swS + (lane>>2), rl1 = rl0 + 8;
  int sg0 = sBase + rl0, sg1 = sBase + rl1;
  float inv0 = 1.0f / g_rowsum[dir][b][sg0];
  float inv1 = 1.0f / g_rowsum[dir][b][sg1];
  #pragma unroll
  for (int nt=0;nt<4;nt++){
    int col = twD + nt*8 + 2*(lane&3);
    int dg = dBase + col;
    *(float2*)&g_h[dir][b][sg0][dg] = make_float2(acc[nt][0]*inv0, acc[nt][1]*inv0);
    *(float2*)&g_h[dir][b][sg1][dg] = make_float2(acc[nt][2]*inv1, acc[nt][3]*inv1);
  }
}

// ---------------- K_epi (R14 version) ----------------
__global__ void __launch_bounds__(64) k_epi(const float* __restrict__ P,
                                            const float* __restrict__ Q,
                                            float* __restrict__ out){
  int s = blockIdx.x, b = blockIdx.y;
  int tid=threadIdx.x;
  int dir = tid>>5, lane = tid&31;
  const float* p  = P + (size_t)(s*NB+b)*512 + dir*256;
  int qpos = dir ? 0 : (S-1);
  const float* qf = Q + (size_t)(qpos*NB+b)*512 + dir*256;
  ull key = g_pack[dir][b][s];
  int ts = (int)(0xFFFFFFFFu - (uint)(key & 0xFFFFFFFFu));
  const float* qm = Q + (size_t)(ts*NB+b)*512 + dir*256;
  const float* h  = &g_h[dir][b][s][0];
  float aF[8], aA[8], aH[8], aM[8];
  #pragma unroll
  for (int l=0;l<8;l++){ aF[l]=0.f;aA[l]=0.f;aH[l]=0.f;aM[l]=0.f; }
  #pragma unroll
  for (int k=0;k<8;k++){
    int d = lane + 32*k;
    float pv=p[d], qv=qf[d], hv=h[d], mv=qm[d];
    float pq=pv*qv, ph=pv*hv, hh=hv*hv, pm=pv*mv;
    #pragma unroll
    for (int l=0;l<8;l++){
      aF[l] += pq*g_w2[dir][l][d];
      float w4 = g_w2[4][l][d];
      aA[l] += ph*w4;
      aH[l] += hh*w4;
      aM[l] += pm*g_w2[5][l][d];
    }
  }
  #pragma unroll
  for (int off=16; off; off>>=1){
    #pragma unroll
    for (int l=0;l<8;l++){
      aF[l]+=__shfl_down_sync(0xffffffffu,aF[l],off);
      aA[l]+=__shfl_down_sync(0xffffffffu,aA[l],off);
      aH[l]+=__shfl_down_sync(0xffffffffu,aH[l],off);
      aM[l]+=__shfl_down_sync(0xffffffffu,aM[l],off);
    }
  }
  if (lane==0){
    const float* np_ = &g_np[dir][s][b][0];
    const float* nqf = &g_nq[dir][qpos][b][0];
    const float* nqm = &g_nq[dir][ts][b][0];
    float* o = out + ((size_t)s*NB+b)*64;
    #pragma unroll
    for (int l=0;l<8;l++){
      o[0  + dir*8 + l] = aF[l] / fmaxf(np_[l]    * nqf[l],       EPS);
      o[16 + dir*8 + l] = dec_f(g_mp[dir][b][s][l]);
      o[32 + dir*8 + l] = aA[l] / fmaxf(np_[16+l] * sqrtf(aH[l]), EPS);
      o[48 + dir*8 + l] = aM[l] / fmaxf(np_[24+l] * nqm[24+l],    EPS);
    }
  }
}

extern "C" void kernel_launch(void* const* d_in, const int* in_sizes, int n_in,
                              void* d_out, int out_size){
  const float* P = (const float*)d_in[0];
  const float* Q = (const float*)d_in[1];
  const float* W = (const float*)d_in[2];
  float* out = (float*)d_out;

  cudaFuncSetAttribute(k_main_mma,  cudaFuncAttributeMaxDynamicSharedMemorySize, SM_MM);
  cudaFuncSetAttribute(k_hmean_mma, cudaFuncAttributeMaxDynamicSharedMemorySize, SM_HM);

  k_w2<<<12, 1024>>>(W);
  k_init<<<512, 1024>>>();
  k_split<<<dim3(8, NB, 2), 256>>>(Q);
  k_norms<<<dim3(1024, 2, 2), 128>>>(P, Q);
  k_main_mma<<<dim3(8, NB, 2), 256, SM_MM>>>(P, out);
  k_hmean_mma<<<dim3(16, NB, 2), 256, SM_HM>>>();
  k_epi<<<dim3(S, NB), 64>>>(P, Q, out);
}

// round 17
// speedup vs baseline: 1.0638x; 1.0414x over previous
#include <cuda_runtime.h>
#include <cuda_fp16.h>
#include <math.h>
#include <stdint.h>

#define S 256
#define NB 128
#define D 256
#define L 8
#define EPS 1e-8f
typedef unsigned long long ull;
typedef unsigned int uint;

#define FMA2(d_, a_, b_, c_) asm("fma.rn.f32x2 %0, %1, %2, %3;" : "=l"(d_) : "l"(a_), "l"(b_), "l"(c_))
#define ADD2(d_, a_, b_) asm("add.rn.f32x2 %0, %1, %2;" : "=l"(d_) : "l"(a_), "l"(b_))
#define UNPACK2(lo_, hi_, p_) asm("mov.b64 {%0, %1}, %2;" : "=f"(lo_), "=f"(hi_) : "l"(p_))

#define LDX4(r, addr) \
  asm volatile("ldmatrix.sync.aligned.m8n8.x4.shared.b16 {%0,%1,%2,%3}, [%4];" \
    : "=r"((r)[0]),"=r"((r)[1]),"=r"((r)[2]),"=r"((r)[3]) : "r"(addr))

#define MMAH(d, a, b0_, b1_) \
  asm volatile("mma.sync.aligned.m16n8k16.row.col.f32.f16.f16.f32 " \
    "{%0,%1,%2,%3}, {%4,%5,%6,%7}, {%8,%9}, {%0,%1,%2,%3};" \
    : "+f"((d)[0]),"+f"((d)[1]),"+f"((d)[2]),"+f"((d)[3]) \
    : "r"((a)[0]),"r"((a)[1]),"r"((a)[2]),"r"((a)[3]), "r"(b0_),"r"(b1_))

__device__ __forceinline__ uint32_t smem_u32(const void* p){
  uint32_t a;
  asm("{ .reg .u64 t; cvta.to.shared.u64 t, %1; cvt.u32.u64 %0, t; }" : "=r"(a) : "l"(p));
  return a;
}
__device__ __forceinline__ uint enc_f(float x){
  uint u = __float_as_uint(x);
  return (u & 0x80000000u) ? ~u : (u | 0x80000000u);
}
__device__ __forceinline__ float dec_f(uint u){
  return __uint_as_float((u & 0x80000000u) ? (u & 0x7FFFFFFFu) : ~u);
}
__device__ __forceinline__ uint packh(__half a, __half b){
  return (uint)__half_as_ushort(a) | ((uint)__half_as_ushort(b) << 16);
}

// ---- scratch ----
__device__ __align__(16) float g_w2[6][L][D];
__device__ __align__(16) float g_np[2][S][NB][33];
__device__ __align__(16) float g_nq[2][S][NB][33];
__device__ __align__(16) float g_alpha[2][NB][S][S];
__device__ __align__(16) float g_rowsum[2][NB][S];
__device__ __align__(16) ull   g_pack[2][NB][S];
__device__ __align__(16) uint  g_mp[2][NB][S][L];
__device__ __align__(16) float g_h[2][NB][S][D];
__device__ __align__(16) __half g_qhi[2][NB][S][D];   // [t][d]
__device__ __align__(16) __half g_qlo[2][NB][S][D];
__device__ __align__(16) __half g_qthi[2][NB][D][S];  // [d][t]

// ---------------- K0: W^2 ----------------
__global__ void k_w2(const float* __restrict__ W){
  int i = blockIdx.x*blockDim.x + threadIdx.x;
  if (i < 6*L*D){ float w = W[i]; (&g_w2[0][0][0])[i] = w*w; }
}

// ---------------- k_init ----------------
__global__ void k_init(){
  int i = blockIdx.x*1024 + threadIdx.x;
  if (i < 2*NB*S*L) (&g_mp[0][0][0][0])[i] = 0u;
  if (i < 2*NB*S){
    (&g_pack[0][0][0])[i] = 0ULL;
    (&g_rowsum[0][0][0])[i] = 0.f;
  }
}

// ---------------- k_split: Q -> fp16 hi/lo + transposed hi ----------------
__global__ void __launch_bounds__(256) k_split(const float* __restrict__ Q){
  __shared__ unsigned short sth[256*33];
  int b = blockIdx.y, dir = blockIdx.z;
  int tid = threadIdx.x;
  int tl = tid>>3, d0 = (tid&7)*32;
  int t = blockIdx.x*32 + tl;
  const float4* src = (const float4*)(Q + (size_t)(t*NB + b)*512 + dir*256 + d0);
  unsigned short hbuf[32], lbuf[32];
  #pragma unroll
  for (int k=0;k<8;k++){
    float4 v = src[k];
    float xs[4] = {v.x, v.y, v.z, v.w};
    #pragma unroll
    for (int j=0;j<4;j++){
      __half h = __float2half_rn(xs[j]);
      __half lo = __float2half_rn(xs[j] - __half2float(h));
      int idx = 4*k+j;
      hbuf[idx] = __half_as_ushort(h);
      lbuf[idx] = __half_as_ushort(lo);
      sth[(d0+idx)*33 + tl] = hbuf[idx];
    }
  }
  size_t qi = ((size_t)(dir*NB+b)*256 + t)*256 + d0;
  #pragma unroll
  for (int k=0;k<4;k++){
    ((uint4*)(&g_qhi[0][0][0][0] + qi))[k] = ((uint4*)hbuf)[k];
    ((uint4*)(&g_qlo[0][0][0][0] + qi))[k] = ((uint4*)lbuf)[k];
  }
  __syncthreads();
  int d = tid;
  unsigned short th[32];
  #pragma unroll
  for (int j=0;j<32;j++) th[j]=sth[d*33+j];
  size_t qti = ((size_t)(dir*NB+b)*256 + d)*256 + blockIdx.x*32;
  #pragma unroll
  for (int k=0;k<4;k++)
    ((uint4*)(&g_qthi[0][0][0][0] + qti))[k] = ((uint4*)th)[k];
}

// ---------------- K1: weighted norms, GEMM-tiled (R11 winner) ----------------
#define PXP 133
#define PWP 133

__global__ void __launch_bounds__(128) k_norms(const float* __restrict__ P,
                                               const float* __restrict__ Q){
  __shared__ ull sw[32*PWP];
  __shared__ ull sx[32*PXP];
  int tensor = blockIdx.y, dir = blockIdx.z;
  int rBase = blockIdx.x*32;
  const float* X = tensor ? Q : P;
  float* dst = tensor ? &g_nq[0][0][0][0] : &g_np[0][0][0][0];
  int tid = threadIdx.x;
  int wrows[4] = {dir, 2+dir, 4, 5};

  for (int i=tid; i<32*128; i+=128){
    int ch = i>>7, pr128 = i&127;
    int dq = pr128>>5, pr = pr128&31;
    int a = ch>>3, l = ch&7;
    float2 w = *(const float2*)&g_w2[wrows[a]][l][2*pr128];
    *(float2*)&sw[ch*PWP + dq*33 + pr] = w;
  }
  {
    int r = tid>>2, q = tid&3;
    const float4* src = (const float4*)(X + (size_t)(rBase+r)*512 + dir*256 + q*64);
    ull* xrow = sx + r*PXP + q*33;
    #pragma unroll
    for (int k=0;k<16;k++){
      float4 v = src[k];
      *(float2*)&xrow[2*k]   = make_float2(v.x*v.x, v.y*v.y);
      *(float2*)&xrow[2*k+1] = make_float2(v.z*v.z, v.w*v.w);
    }
  }
  __syncthreads();

  int dq = tid&3, cg = (tid>>2)&3, rg = tid>>4;
  const ull* xrows[4];
  #pragma unroll
  for (int i=0;i<4;i++) xrows[i] = sx + (rg*4+i)*PXP + dq*33;
  const ull* wbase = sw + (cg*8)*PWP + dq*33;

  ull acc[4][8];
  ull uacc[4];
  #pragma unroll
  for (int i=0;i<4;i++){
    uacc[i]=0ULL;
    #pragma unroll
    for (int l=0;l<8;l++) acc[i][l]=0ULL;
  }
  #pragma unroll 4
  for (int pr=0; pr<32; pr++){
    ull xv[4];
    #pragma unroll
    for (int i=0;i<4;i++) xv[i] = xrows[i][pr];
    if (cg==0){
      #pragma unroll
      for (int i=0;i<4;i++) ADD2(uacc[i], uacc[i], xv[i]);
    }
    #pragma unroll
    for (int l=0;l<8;l++){
      ull w = wbase[l*PWP + pr];
      #pragma unroll
      for (int i=0;i<4;i++) FMA2(acc[i][l], xv[i], w, acc[i][l]);
    }
  }
  #pragma unroll
  for (int i=0;i<4;i++){
    float v[9];
    #pragma unroll
    for (int l=0;l<8;l++){
      float lo,hi; UNPACK2(lo,hi,acc[i][l]);
      v[l] = lo+hi;
    }
    { float lo,hi; UNPACK2(lo,hi,uacc[i]); v[8] = lo+hi; }
    #pragma unroll
    for (int off=1; off<4; off<<=1){
      #pragma unroll
      for (int l=0;l<9;l++) v[l] += __shfl_xor_sync(0xffffffffu, v[l], off);
    }
    if (dq==0){
      int r = rBase + rg*4 + i;
      float* o = dst + ((size_t)(dir*S*NB) + r)*33;
      #pragma unroll
      for (int l=0;l<8;l++) o[cg*8+l] = sqrtf(v[l]);
      if (cg==0) o[32] = sqrtf(v[8]);
    }
  }
}

// ---------------- k_main_mma: channel-paired maxpool + 3-term alpha (R14) ----------------
#define BPITCH 528
#define OFF_BHI 0
#define OFF_BLO 67584
#define OFF_AHI 135168
#define OFF_ALO 168960
#define OFF_W2S 202752
#define OFF_QNS 210944
#define OFF_PNS 215552
#define SM_MM   217856

__global__ void __launch_bounds__(256) k_main_mma(const float* __restrict__ P,
                                                  float* __restrict__ out){
  extern __shared__ char smem[];
  float* sW2 = (float*)(smem + OFF_W2S);
  float* sQn = (float*)(smem + OFF_QNS);
  float* sPn = (float*)(smem + OFF_PNS);

  int sTile = blockIdx.x >> 1, tHalf = blockIdx.x & 1;
  int b = blockIdx.y, dir = blockIdx.z;
  int sBase = sTile*64, tBase = tHalf*128;
  int tid = threadIdx.x, wid = tid>>5, lane = tid&31;
  int swS = (wid>>1)*16;
  int twT = (wid&1)*64;

  for (int i=tid;i<8*256;i+=256) sW2[i] = g_w2[2+dir][0][i];
  for (int i=tid;i<9*128;i+=256){
    int c=i>>7, t=i&127;
    sQn[i] = 1.0f / g_nq[dir][tBase+t][b][(c<8)?(8+c):32];
  }
  for (int i=tid;i<9*64;i+=256){
    int c=i/64, r=i%64;
    sPn[i] = 1.0f / g_np[dir][sBase+r][b][(c<8)?(8+c):32];
  }
  { // B tiles: q hi/lo fp16 [128 t][256 d]
    int r = tid>>1, h = tid&1;
    size_t qi = ((size_t)(dir*NB+b)*256 + tBase + r)*256 + h*128;
    const uint4* shi = (const uint4*)(&g_qhi[0][0][0][0] + qi);
    const uint4* slo = (const uint4*)(&g_qlo[0][0][0][0] + qi);
    char* dh = smem + OFF_BHI + r*BPITCH + h*256;
    char* dl = smem + OFF_BLO + r*BPITCH + h*256;
    #pragma unroll
    for (int k=0;k<16;k++){
      *(uint4*)(dh + 16*k) = shi[k];
      *(uint4*)(dl + 16*k) = slo[k];
    }
  }
  float preg[64];
  int prow = tid>>2, pcb = tid&3;
  {
    const float4* src = (const float4*)(P + ((size_t)(sBase+prow)*NB + b)*512 + dir*256 + pcb*64);
    #pragma unroll
    for (int k=0;k<16;k++){
      float4 v = src[k];
      preg[4*k+0]=v.x; preg[4*k+1]=v.y; preg[4*k+2]=v.z; preg[4*k+3]=v.w;
    }
  }

  uint32_t aHb = smem_u32(smem + OFF_AHI);
  uint32_t aLb = smem_u32(smem + OFF_ALO);
  uint32_t bHb = smem_u32(smem + OFF_BHI);
  uint32_t bLb = smem_u32(smem + OFF_BLO);

  uint32_t arow = swS + (lane&15);
  uint32_t acolx = ((lane&16)?16:0);
  uint32_t aoffH = aHb + arow*BPITCH + acolx;
  uint32_t aoffL = aLb + arow*BPITCH + acolx;
  uint32_t brow_b = (lane&7) + ((lane&16)>>1);
  uint32_t bcolx = ((lane&8)?16:0);

  int rl0 = swS + (lane>>2), rl1 = rl0 + 8;

  for (int pg=0; pg<5; pg++){
    __syncthreads();
    if (pg < 4){
      int c0 = pg*2, c1 = c0+1;
      {
        char* dh = smem + OFF_AHI + prow*BPITCH + pcb*128;
        char* dl = smem + OFF_ALO + prow*BPITCH + pcb*128;
        const float* w0 = sW2 + c0*256 + pcb*64;
        const float* w1 = sW2 + c1*256 + pcb*64;
        #pragma unroll
        for (int j=0;j<16;j++){
          __half a0 = __float2half_rn(preg[4*j+0]*w0[4*j+0]);
          __half a1 = __float2half_rn(preg[4*j+1]*w0[4*j+1]);
          __half a2 = __float2half_rn(preg[4*j+2]*w0[4*j+2]);
          __half a3 = __float2half_rn(preg[4*j+3]*w0[4*j+3]);
          __half b0 = __float2half_rn(preg[4*j+0]*w1[4*j+0]);
          __half b1 = __float2half_rn(preg[4*j+1]*w1[4*j+1]);
          __half b2 = __float2half_rn(preg[4*j+2]*w1[4*j+2]);
          __half b3 = __float2half_rn(preg[4*j+3]*w1[4*j+3]);
          *(uint2*)(dh + 8*j) = make_uint2(packh(a0,a1), packh(a2,a3));
          *(uint2*)(dl + 8*j) = make_uint2(packh(b0,b1), packh(b2,b3));
        }
      }
      __syncthreads();

      float acc0[8][4], acc1[8][4];
      #pragma unroll
      for (int nt=0;nt<8;nt++){
        acc0[nt][0]=0.f;acc0[nt][1]=0.f;acc0[nt][2]=0.f;acc0[nt][3]=0.f;
        acc1[nt][0]=0.f;acc1[nt][1]=0.f;acc1[nt][2]=0.f;acc1[nt][3]=0.f;
      }
      for (int kc=0; kc<16; kc++){
        uint32_t a0[4], a1[4];
        LDX4(a0, aoffH + kc*32);
        LDX4(a1, aoffL + kc*32);
        uint32_t bh[4][4];
        #pragma unroll
        for (int g=0; g<4; g++){
          uint32_t boff = (twT + g*16 + brow_b)*BPITCH + kc*32 + bcolx;
          LDX4(bh[g], bHb + boff);
        }
        #pragma unroll
        for (int g=0; g<4; g++){
          MMAH(acc0[2*g],   a0, bh[g][0], bh[g][1]);
          MMAH(acc0[2*g+1], a0, bh[g][2], bh[g][3]);
        }
        #pragma unroll
        for (int g=0; g<4; g++){
          MMAH(acc1[2*g],   a1, bh[g][0], bh[g][1]);
          MMAH(acc1[2*g+1], a1, bh[g][2], bh[g][3]);
        }
      }
      #pragma unroll
      for (int ci=0; ci<2; ci++){
        int c = c0 + ci;
        float (*ac)[4] = ci ? acc1 : acc0;
        float m0=-3.4e38f, m1=-3.4e38f;
        const float* qn = sQn + c*128;
        #pragma unroll
        for (int nt=0;nt<8;nt++){
          int col = twT + nt*8 + 2*(lane&3);
          float q0 = qn[col], q1 = qn[col+1];
          m0 = fmaxf(m0, fmaxf(ac[nt][0]*q0, ac[nt][1]*q1));
          m1 = fmaxf(m1, fmaxf(ac[nt][2]*q0, ac[nt][3]*q1));
        }
        #pragma unroll
        for (int off=1; off<4; off<<=1){
          m0 = fmaxf(m0, __shfl_xor_sync(0xffffffffu, m0, off));
          m1 = fmaxf(m1, __shfl_xor_sync(0xffffffffu, m1, off));
        }
        if ((lane&3)==0){
          atomicMax(&g_mp[dir][b][sBase+rl0][c], enc_f(m0 * sPn[c*64+rl0]));
          atomicMax(&g_mp[dir][b][sBase+rl1][c], enc_f(m1 * sPn[c*64+rl1]));
        }
      }
    } else {
      {
        char* dh = smem + OFF_AHI + prow*BPITCH + pcb*128;
        char* dl = smem + OFF_ALO + prow*BPITCH + pcb*128;
        #pragma unroll
        for (int j=0;j<16;j++){
          float a0=preg[4*j+0], a1=preg[4*j+1], a2=preg[4*j+2], a3=preg[4*j+3];
          __half h0 = __float2half_rn(a0), h1 = __float2half_rn(a1);
          __half h2 = __float2half_rn(a2), h3 = __float2half_rn(a3);
          __half l0 = __float2half_rn(a0 - __half2float(h0));
          __half l1 = __float2half_rn(a1 - __half2float(h1));
          __half l2 = __float2half_rn(a2 - __half2float(h2));
          __half l3 = __float2half_rn(a3 - __half2float(h3));
          *(uint2*)(dh + 8*j) = make_uint2(packh(h0,h1), packh(h2,h3));
          *(uint2*)(dl + 8*j) = make_uint2(packh(l0,l1), packh(l2,l3));
        }
      }
      __syncthreads();

      float acc[8][4];
      #pragma unroll
      for (int nt=0;nt<8;nt++){ acc[nt][0]=0.f;acc[nt][1]=0.f;acc[nt][2]=0.f;acc[nt][3]=0.f; }

      for (int kc=0; kc<16; kc++){
        uint32_t ah[4], al[4];
        LDX4(ah, aoffH + kc*32);
        LDX4(al, aoffL + kc*32);
        uint32_t bh[4][4], bl[4][4];
        #pragma unroll
        for (int g=0; g<4; g++){
          uint32_t boff = (twT + g*16 + brow_b)*BPITCH + kc*32 + bcolx;
          LDX4(bh[g], bHb + boff);
          LDX4(bl[g], bLb + boff);
        }
        #pragma unroll
        for (int g=0; g<4; g++){
          MMAH(acc[2*g],   ah, bh[g][0], bh[g][1]);
          MMAH(acc[2*g+1], ah, bh[g][2], bh[g][3]);
        }
        #pragma unroll
        for (int g=0; g<4; g++){
          MMAH(acc[2*g],   ah, bl[g][0], bl[g][1]);
          MMAH(acc[2*g+1], ah, bl[g][2], bl[g][3]);
        }
        #pragma unroll
        for (int g=0; g<4; g++){
          MMAH(acc[2*g],   al, bh[g][0], bh[g][1]);
          MMAH(acc[2*g+1], al, bh[g][2], bh[g][3]);
        }
      }

      float invp0 = sPn[8*64 + rl0], invp1 = sPn[8*64 + rl1];
      const float* qn = sQn + 8*128;
      float rs0=0.f, rs1=0.f, bv0=-3.4e38f, bv1=-3.4e38f;
      int bi0=0, bi1=0;
      int sg0 = sBase + rl0, sg1 = sBase + rl1;
      float* arow0 = &g_alpha[dir][b][sg0][tBase];
      float* arow1 = &g_alpha[dir][b][sg1][tBase];
      #pragma unroll
      for (int nt=0;nt<8;nt++){
        int col = twT + nt*8 + 2*(lane&3);
        float q0 = qn[col], q1 = qn[col+1];
        float a00 = acc[nt][0]*q0*invp0, a01 = acc[nt][1]*q1*invp0;
        float a10 = acc[nt][2]*q0*invp1, a11 = acc[nt][3]*q1*invp1;
        *(float2*)(arow0 + col) = make_float2(a00, a01);
        *(float2*)(arow1 + col) = make_float2(a10, a11);
        rs0 += a00 + a01; rs1 += a10 + a11;
        int tg = tBase + col;
        if (a00>bv0){bv0=a00;bi0=tg;}
        if (a01>bv0){bv0=a01;bi0=tg+1;}
        if (a10>bv1){bv1=a10;bi1=tg;}
        if (a11>bv1){bv1=a11;bi1=tg+1;}
      }
      #pragma unroll
      for (int off=1; off<4; off<<=1){
        rs0 += __shfl_xor_sync(0xffffffffu, rs0, off);
        rs1 += __shfl_xor_sync(0xffffffffu, rs1, off);
        float ov0 = __shfl_xor_sync(0xffffffffu, bv0, off);
        int   oi0 = __shfl_xor_sync(0xffffffffu, bi0, off);
        if (ov0>bv0 || (ov0==bv0 && oi0<bi0)){bv0=ov0;bi0=oi0;}
        float ov1 = __shfl_xor_sync(0xffffffffu, bv1, off);
        int   oi1 = __shfl_xor_sync(0xffffffffu, bi1, off);
        if (ov1>bv1 || (ov1==bv1 && oi1<bi1)){bv1=ov1;bi1=oi1;}
      }
      if ((lane&3)==0){
        atomicAdd(&g_rowsum[dir][b][sg0], rs0);
        atomicAdd(&g_rowsum[dir][b][sg1], rs1);
        atomicMax(&g_pack[dir][b][sg0], ((ull)enc_f(bv0)<<32) | (uint)(0xFFFFFFFFu - (uint)bi0));
        atomicMax(&g_pack[dir][b][sg1], ((ull)enc_f(bv1)<<32) | (uint)(0xFFFFFFFFu - (uint)bi1));
      }
    }
  }
}

// ---------------- k_hmean_mma: 64s x 128d CTA, single-term alpha, 2 CTAs/SM ----------------
// grid (8 = 4 sTiles x 2 dHalves, NB, 2). smem = 67584 + 33792 = 101376.
#define HM_BHI 0
#define HM_AHI 67584
#define SM_HM  101376

__global__ void __launch_bounds__(256) k_hmean_mma(void){
  extern __shared__ char smem[];
  int sTile = blockIdx.x >> 1, dHalf = blockIdx.x & 1;
  int b = blockIdx.y, dir = blockIdx.z;
  int sBase = sTile*64, dBase = dHalf*128;
  int tid = threadIdx.x, wid = tid>>5, lane = tid&31;
  int swS = (wid>>1)*16, twD = (wid&1)*64;

  { // B: qthi [128 d rows][256 t]
    int r = tid>>1, h = tid&1;
    size_t qi = ((size_t)(dir*NB+b)*256 + dBase + r)*256 + h*128;
    const uint4* shi = (const uint4*)(&g_qthi[0][0][0][0] + qi);
    char* dh = smem + HM_BHI + r*BPITCH + h*256;
    #pragma unroll
    for (int k=0;k<16;k++) *(uint4*)(dh + 16*k) = shi[k];
  }
  { // A: alpha [64 s][256 t] fp32 -> fp16 (single term)
    int prow = tid>>2, pcb = tid&3;
    const float* arow_g = &g_alpha[dir][b][sBase+prow][pcb*64];
    char* dh = smem + HM_AHI + prow*BPITCH + pcb*128;
    #pragma unroll
    for (int j=0;j<16;j++){
      float4 v = *(const float4*)(arow_g + 4*j);
      __half h0 = __float2half_rn(v.x), h1 = __float2half_rn(v.y);
      __half h2 = __float2half_rn(v.z), h3 = __float2half_rn(v.w);
      *(uint2*)(dh + 8*j) = make_uint2(packh(h0,h1), packh(h2,h3));
    }
  }
  __syncthreads();

  uint32_t aHb = smem_u32(smem + HM_AHI);
  uint32_t bHb = smem_u32(smem + HM_BHI);
  uint32_t arow = swS + (lane&15);
  uint32_t acolx = ((lane&16)?16:0);
  uint32_t aoffH = aHb + arow*BPITCH + acolx;
  uint32_t brow_b = (lane&7) + ((lane&16)>>1);
  uint32_t bcolx = ((lane&8)?16:0);

  float acc[8][4];
  #pragma unroll
  for (int nt=0;nt<8;nt++){ acc[nt][0]=0.f;acc[nt][1]=0.f;acc[nt][2]=0.f;acc[nt][3]=0.f; }

  for (int kc=0; kc<16; kc++){
    uint32_t ah[4];
    LDX4(ah, aoffH + kc*32);
    uint32_t bh[4][4];
    #pragma unroll
    for (int g=0; g<4; g++){
      uint32_t boff = (twD + g*16 + brow_b)*BPITCH + kc*32 + bcolx;
      LDX4(bh[g], bHb + boff);
    }
    #pragma unroll
    for (int g=0; g<4; g++){
      MMAH(acc[2*g],   ah, bh[g][0], bh[g][1]);
      MMAH(acc[2*g+1], ah, bh[g][2], bh[g][3]);
    }
  }

  int rl0 = swS + (lane>>2), rl1 = rl0 + 8;
  int sg0 = sBase + rl0, sg1 = sBase + rl1;
  float inv0 = 1.0f / g_rowsum[dir][b][sg0];
  float inv1 = 1.0f / g_rowsum[dir][b][sg1];
  #pragma unroll
  for (int nt=0;nt<8;nt++){
    int col = twD + nt*8 + 2*(lane&3);
    int dg = dBase + col;
    *(float2*)&g_h[dir][b][sg0][dg] = make_float2(acc[nt][0]*inv0, acc[nt][1]*inv0);
    *(float2*)&g_h[dir][b][sg1][dg] = make_float2(acc[nt][2]*inv1, acc[nt][3]*inv1);
  }
}

// ---------------- K_epi (R14 version) ----------------
__global__ void __launch_bounds__(64) k_epi(const float* __restrict__ P,
                                            const float* __restrict__ Q,
                                            float* __restrict__ out){
  int s = blockIdx.x, b = blockIdx.y;
  int tid=threadIdx.x;
  int dir = tid>>5, lane = tid&31;
  const float* p  = P + (size_t)(s*NB+b)*512 + dir*256;
  int qpos = dir ? 0 : (S-1);
  const float* qf = Q + (size_t)(qpos*NB+b)*512 + dir*256;
  ull key = g_pack[dir][b][s];
  int ts = (int)(0xFFFFFFFFu - (uint)(key & 0xFFFFFFFFu));
  const float* qm = Q + (size_t)(ts*NB+b)*512 + dir*256;
  const float* h  = &g_h[dir][b][s][0];
  float aF[8], aA[8], aH[8], aM[8];
  #pragma unroll
  for (int l=0;l<8;l++){ aF[l]=0.f;aA[l]=0.f;aH[l]=0.f;aM[l]=0.f; }
  #pragma unroll
  for (int k=0;k<8;k++){
    int d = lane + 32*k;
    float pv=p[d], qv=qf[d], hv=h[d], mv=qm[d];
    float pq=pv*qv, ph=pv*hv, hh=hv*hv, pm=pv*mv;
    #pragma unroll
    for (int l=0;l<8;l++){
      aF[l] += pq*g_w2[dir][l][d];
      float w4 = g_w2[4][l][d];
      aA[l] += ph*w4;
      aH[l] += hh*w4;
      aM[l] += pm*g_w2[5][l][d];
    }
  }
  #pragma unroll
  for (int off=16; off; off>>=1){
    #pragma unroll
    for (int l=0;l<8;l++){
      aF[l]+=__shfl_down_sync(0xffffffffu,aF[l],off);
      aA[l]+=__shfl_down_sync(0xffffffffu,aA[l],off);
      aH[l]+=__shfl_down_sync(0xffffffffu,aH[l],off);
      aM[l]+=__shfl_down_sync(0xffffffffu,aM[l],off);
    }
  }
  if (lane==0){
    const float* np_ = &g_np[dir][s][b][0];
    const float* nqf = &g_nq[dir][qpos][b][0];
    const float* nqm = &g_nq[dir][ts][b][0];
    float* o = out + ((size_t)s*NB+b)*64;
    #pragma unroll
    for (int l=0;l<8;l++){
      o[0  + dir*8 + l] = aF[l] / fmaxf(np_[l]    * nqf[l],       EPS);
      o[16 + dir*8 + l] = dec_f(g_mp[dir][b][s][l]);
      o[32 + dir*8 + l] = aA[l] / fmaxf(np_[16+l] * sqrtf(aH[l]), EPS);
      o[48 + dir*8 + l] = aM[l] / fmaxf(np_[24+l] * nqm[24+l],    EPS);
    }
  }
}

extern "C" void kernel_launch(void* const* d_in, const int* in_sizes, int n_in,
                              void* d_out, int out_size){
  const float* P = (const float*)d_in[0];
  const float* Q = (const float*)d_in[1];
  const float* W = (const float*)d_in[2];
  float* out = (float*)d_out;

  cudaFuncSetAttribute(k_main_mma,  cudaFuncAttributeMaxDynamicSharedMemorySize, SM_MM);
  cudaFuncSetAttribute(k_hmean_mma, cudaFuncAttributeMaxDynamicSharedMemorySize, SM_HM);

  k_w2<<<12, 1024>>>(W);
  k_init<<<512, 1024>>>();
  k_split<<<dim3(8, NB, 2), 256>>>(Q);
  k_norms<<<dim3(1024, 2, 2), 128>>>(P, Q);
  k_main_mma<<<dim3(8, NB, 2), 256, SM_MM>>>(P, out);
  k_hmean_mma<<<dim3(8, NB, 2), 256, SM_HM>>>();
  k_epi<<<dim3(S, NB), 64>>>(P, Q, out);
}